// round 17
// baseline (speedup 1.0000x reference)
#include <cuda_runtime.h>
#include <cuda_fp16.h>
#include <math.h>
#include <stdint.h>

// Fixed problem shape: n=8192, k=128, h=128
#define N_FIX 8192
#define KDIM 128
#define BM 128
#define BK 32
#define RBLKS (N_FIX / BM)            // 64 row blocks
#define KCH (N_FIX / BK)              // 256 k-chunks per row block
#define TOTAL_CHUNKS (RBLKS * KCH)    // 16384
#define GRID 296                      // 148 SMs x 2 CTAs
#define BASE_CNT (TOTAL_CHUNKS / GRID)        // 55
#define EXTRA (TOTAL_CHUNKS - GRID * BASE_CNT) // 104 CTAs get 56
#define STAGES 4
#define STAGE_BYTES 24576             // 16KB A (128x32 fp32) + 8KB B (32x128 f16)
#define BOFF_IN_STAGE 16384
#define SMEM_BYTES (STAGES * STAGE_BYTES)  // 96KB

// ---------------- device scratch ----------------
__device__ __align__(16) __half g_Cb[(size_t)N_FIX * KDIM];
__device__ float g_d[N_FIX];     // row sums of A (atomic partials)
__device__ float g_h2[N_FIX];    // ||H_i||^2
__device__ float g_col[KDIM];
__device__ float g_diag[KDIM];
__device__ int g_cnt;

// ---------------- helpers ----------------
__device__ __forceinline__ uint32_t smem_u32(const void* p) {
    uint32_t a;
    asm("{ .reg .u64 t; cvta.to.shared.u64 t, %1; cvt.u32.u64 %0, t; }" : "=r"(a) : "l"(p));
    return a;
}
__device__ __forceinline__ void cp16(uint32_t saddr, const void* gp) {
    unsigned long long g = __cvta_generic_to_global(gp);
    asm volatile("cp.async.cg.shared.global [%0], [%1], 16;" :: "r"(saddr), "l"(g) : "memory");
}
#define CP_COMMIT() asm volatile("cp.async.commit_group;" ::: "memory")
#define CP_WAIT2()  asm volatile("cp.async.wait_group 2;" ::: "memory")

__device__ __forceinline__ uint32_t cvt_h2(float2 v) {
    __half2 h = __floats2half2_rn(v.x, v.y);
    return *reinterpret_cast<uint32_t*>(&h);
}
__device__ __forceinline__ void ldmx4t(uint32_t& r0, uint32_t& r1, uint32_t& r2,
                                       uint32_t& r3, uint32_t addr) {
    asm volatile("ldmatrix.sync.aligned.m8n8.x4.trans.shared.b16 {%0,%1,%2,%3}, [%4];"
                 : "=r"(r0), "=r"(r1), "=r"(r2), "=r"(r3) : "r"(addr));
}
__device__ __forceinline__ void mma16816h(uint32_t* d, const uint32_t* a, uint32_t b0,
                                          uint32_t b1) {
    asm volatile(
        "mma.sync.aligned.m16n8k16.row.col.f16.f16.f16.f16 "
        "{%0,%1}, {%2,%3,%4,%5}, {%6,%7}, {%0,%1};"
        : "+r"(d[0]), "+r"(d[1])
        : "r"(a[0]), "r"(a[1]), "r"(a[2]), "r"(a[3]), "r"(b0), "r"(b1));
}

// ---------------- prep: init, C->f16, ||H_i||^2 ----------------
__global__ void __launch_bounds__(256) k_prep(const float* __restrict__ C,
                                              const float* __restrict__ H) {
    const int b = blockIdx.x, tid = threadIdx.x;
    if (b == 0) {
        if (tid < KDIM) { g_col[tid] = 0.0f; g_diag[tid] = 0.0f; }
        if (tid == 0) g_cnt = 0;
    }
    if (tid < 32) g_d[b * 32 + tid] = 0.0f;

    size_t base = ((size_t)b * 256 + tid) * 16;
    const float4* src = reinterpret_cast<const float4*>(C + base);
    uint32_t o[8];
#pragma unroll
    for (int q = 0; q < 4; ++q) {
        float4 v = __ldg(&src[q]);
        o[q * 2 + 0] = cvt_h2(make_float2(v.x, v.y));
        o[q * 2 + 1] = cvt_h2(make_float2(v.z, v.w));
    }
    uint4* dst = reinterpret_cast<uint4*>(g_Cb + base);
    dst[0] = make_uint4(o[0], o[1], o[2], o[3]);
    dst[1] = make_uint4(o[4], o[5], o[6], o[7]);

    const int row = b * 32 + (tid >> 3);
    const float4* hp = reinterpret_cast<const float4*>(H + (size_t)row * KDIM + (tid & 7) * 16);
    float h2 = 0.0f;
#pragma unroll
    for (int q = 0; q < 4; ++q) {
        float4 v = __ldg(&hp[q]);
        h2 += v.x * v.x + v.y * v.y + v.z * v.z + v.w * v.w;
    }
    h2 += __shfl_xor_sync(0xffffffffu, h2, 1);
    h2 += __shfl_xor_sync(0xffffffffu, h2, 2);
    h2 += __shfl_xor_sync(0xffffffffu, h2, 4);
    if ((tid & 7) == 0) g_h2[row] = h2;
}

// ---------------- stream-K GEMM (BM=128, f16 acc) + fused reductions + final ----------------
__global__ void __launch_bounds__(256, 2) k_gemm(const float* __restrict__ A,
                                                 const float* __restrict__ C,
                                                 const float* __restrict__ papra,
                                                 const int* __restrict__ flag,
                                                 float* __restrict__ out, int out_size) {
    extern __shared__ __align__(1024) char smem[];
    __shared__ float scol[KDIM], sdiag[KDIM], swarp[8];
    __shared__ int is_last;

    const int tid = threadIdx.x, lane = tid & 31, wid = tid >> 5;
    const int wm = wid & 3, wn = wid >> 2;        // 4 M-warps (m32) x 2 N-warps (n64)
    const uint32_t su = smem_u32(smem);

    if (tid < KDIM) { scol[tid] = 0.0f; sdiag[tid] = 0.0f; }

    // ---- stream-K span ----
    const int b = blockIdx.x;
    const int start = b * BASE_CNT + (b < EXTRA ? b : EXTRA);
    const int cnt = BASE_CNT + (b < EXTRA ? 1 : 0);
    const int end = start + cnt;

    // ---- cp.async per-thread bases ----
    const int rA0 = tid >> 3, cA0 = tid & 7;
    const uint32_t soA0 = (uint32_t)(rA0 * 128 + ((cA0 * 16) ^ ((rA0 & 3) << 5)));
    const float* gA_base = A + (size_t)rA0 * N_FIX + cA0 * 4;
    const int kB0 = tid >> 4, cB0 = tid & 15;
    const uint32_t soB0 = (uint32_t)(BOFF_IN_STAGE + kB0 * 256 + ((cB0 * 16) ^ ((kB0 & 7) << 4)));
    const __half* gB_base = g_Cb + (size_t)kB0 * KDIM + cB0 * 8;

    // prefetch chunk c into stage sb
#define PREFETCH(c, sb) do {                                                      \
        int _rb = (c) >> 8, _kc = (c) & 255;                                      \
        const float* _a = gA_base + (size_t)(_rb * BM) * N_FIX + _kc * BK;        \
        const __half* _bp = gB_base + (size_t)(_kc * BK) * KDIM;                  \
        _Pragma("unroll")                                                         \
        for (int q = 0; q < 4; ++q)                                               \
            cp16((sb) + soA0 + q * 4096, _a + (size_t)q * 32 * N_FIX);            \
        _Pragma("unroll")                                                         \
        for (int q = 0; q < 2; ++q)                                               \
            cp16((sb) + soB0 + q * 4096, _bp + (size_t)q * 16 * KDIM);            \
    } while (0)

    // ---- fragment offsets ----
    const int r0 = wm * 32 + (lane >> 2);
    const int cb = (lane & 3) * 2;
    uint32_t aoff[2][4];
#pragma unroll
    for (int kq = 0; kq < 2; ++kq) {
#pragma unroll
        for (int q = 0; q < 4; ++q) {
            int rr = r0 + ((q & 1) ? 8 : 0);
            uint32_t coff = (uint32_t)(kq * 64 + cb * 4 + ((q & 2) ? 32 : 0));
            aoff[kq][q] = (uint32_t)(rr * 128) + (coff ^ ((rr & 3) << 5));
        }
    }
    uint32_t boff[4];
    {
        const int mM = lane >> 3, iR = lane & 7;
        const int kkb = (mM & 1) * 8 + iR;
#pragma unroll
        for (int g = 0; g < 4; ++g) {
            int nn = wn * 64 + g * 16 + (mM >> 1) * 8;
            uint32_t off = (uint32_t)(kkb * 256 + nn * 2);
            boff[g] = (uint32_t)BOFF_IN_STAGE + (off ^ ((kkb & 7) << 4));
        }
    }

    uint32_t acc[2][8][2];
#pragma unroll
    for (int mt = 0; mt < 2; ++mt)
#pragma unroll
        for (int t = 0; t < 8; ++t) { acc[mt][t][0] = 0u; acc[mt][t][1] = 0u; }
    float dr[4] = {0.f, 0.f, 0.f, 0.f};

    // flush accumulators for row block RB, then reset (block-uniform call sites only)
#define FLUSH(RB) do {                                                            \
        const int fRow = (RB) * BM;                                               \
        if (wn == 0) {                                                            \
            _Pragma("unroll")                                                     \
            for (int m = 0; m < 4; ++m) {                                         \
                float s = dr[m];                                                  \
                s += __shfl_xor_sync(0xffffffffu, s, 1);                          \
                s += __shfl_xor_sync(0xffffffffu, s, 2);                          \
                if ((lane & 3) == 0)                                              \
                    atomicAdd(&g_d[fRow + r0 + ((m & 1) ? 8 : 0) + (m >> 1) * 16], s); \
            }                                                                     \
        }                                                                         \
        dr[0] = dr[1] = dr[2] = dr[3] = 0.f;                                      \
        _Pragma("unroll")                                                         \
        for (int mt = 0; mt < 2; ++mt)                                            \
        _Pragma("unroll")                                                         \
        for (int t = 0; t < 8; ++t) {                                             \
            const int cbase = wn * 64 + t * 8 + cb;                               \
            const int row = fRow + r0 + mt * 16;                                  \
            float2 c0 = *reinterpret_cast<const float2*>(C + (size_t)row * KDIM + cbase); \
            float2 c1 = *reinterpret_cast<const float2*>(C + (size_t)(row + 8) * KDIM + cbase); \
            float2 m0 = __half22float2(*reinterpret_cast<__half2*>(&acc[mt][t][0])); \
            float2 m1 = __half22float2(*reinterpret_cast<__half2*>(&acc[mt][t][1])); \
            float cs0 = m0.x + m1.x, cs1 = m0.y + m1.y;                           \
            float ds0 = c0.x * m0.x + c1.x * m1.x;                                \
            float ds1 = c0.y * m0.y + c1.y * m1.y;                                \
            _Pragma("unroll")                                                     \
            for (int o = 4; o <= 16; o <<= 1) {                                   \
                cs0 += __shfl_xor_sync(0xffffffffu, cs0, o);                      \
                cs1 += __shfl_xor_sync(0xffffffffu, cs1, o);                      \
                ds0 += __shfl_xor_sync(0xffffffffu, ds0, o);                      \
                ds1 += __shfl_xor_sync(0xffffffffu, ds1, o);                      \
            }                                                                     \
            if ((lane >> 2) == 0) {                                               \
                atomicAdd(&scol[cbase], cs0);                                     \
                atomicAdd(&scol[cbase + 1], cs1);                                 \
                atomicAdd(&sdiag[cbase], ds0);                                    \
                atomicAdd(&sdiag[cbase + 1], ds1);                                \
            }                                                                     \
            acc[mt][t][0] = 0u; acc[mt][t][1] = 0u;                               \
        }                                                                         \
        __syncthreads();                                                          \
        if (tid < KDIM) {                                                         \
            atomicAdd(&g_col[tid], scol[tid]);                                    \
            atomicAdd(&g_diag[tid], sdiag[tid]);                                  \
            scol[tid] = 0.0f; sdiag[tid] = 0.0f;                                  \
        }                                                                         \
        __syncthreads();                                                          \
    } while (0)

    // ---- prologue: fill 3 stages with chunks start..start+2 ----
#pragma unroll
    for (int s = 0; s < STAGES - 1; ++s) {
        if (start + s < end) PREFETCH(start + s, su + s * STAGE_BYTES);
        CP_COMMIT();
    }

    int rb_cur = start >> 8;

    // ---- main loop over the chunk span ----
    for (int j = 0; j < cnt; ++j) {
        const int c = start + j;
        CP_WAIT2();
        __syncthreads();

        const int rb_c = c >> 8;
        if (rb_c != rb_cur) {       // block-uniform
            FLUSH(rb_cur);
            rb_cur = rb_c;
        }
        const uint32_t stg = (uint32_t)((j & (STAGES - 1)) * STAGE_BYTES);

#pragma unroll
        for (int kq = 0; kq < 2; ++kq) {
            uint32_t ra[2][4];
#pragma unroll
            for (int mt = 0; mt < 2; ++mt) {
                float2 fA[4];
#pragma unroll
                for (int q = 0; q < 4; ++q)
                    fA[q] = *reinterpret_cast<const float2*>(
                        smem + stg + aoff[kq][q] + mt * 2048);
                dr[2 * mt + 0] += (fA[0].x + fA[0].y) + (fA[2].x + fA[2].y);
                dr[2 * mt + 1] += (fA[1].x + fA[1].y) + (fA[3].x + fA[3].y);
#pragma unroll
                for (int q = 0; q < 4; ++q) ra[mt][q] = cvt_h2(fA[q]);
            }
#pragma unroll
            for (int g = 0; g < 4; ++g) {
                uint32_t b0, b1, b2, b3;
                ldmx4t(b0, b1, b2, b3, su + stg + boff[g] + kq * 4096);
                mma16816h(acc[0][2 * g], ra[0], b0, b1);
                mma16816h(acc[0][2 * g + 1], ra[0], b2, b3);
                mma16816h(acc[1][2 * g], ra[1], b0, b1);
                mma16816h(acc[1][2 * g + 1], ra[1], b2, b3);
            }
        }

        const int p = c + (STAGES - 1);
        if (p < end)
            PREFETCH(p, su + (uint32_t)(((j + STAGES - 1) & (STAGES - 1)) * STAGE_BYTES));
        CP_COMMIT();
    }

    // ---- final flush ----
    FLUSH(rb_cur);

    // ---- last CTA: sA, h_part, entropy, output ----
    if (tid == 0) {
        __threadfence();
        int c = atomicAdd(&g_cnt, 1);
        is_last = (c == GRID - 1);
    }
    __syncthreads();
    if (is_last) {
        float a1 = 0.0f, a2 = 0.0f;
        for (int i = tid; i < N_FIX; i += 256) {
            float d = __ldcg(&g_d[i]);
            a1 += d * __ldcg(&g_h2[i]);
            a2 += d;
        }
#pragma unroll
        for (int o = 16; o > 0; o >>= 1) {
            a1 += __shfl_xor_sync(0xffffffffu, a1, o);
            a2 += __shfl_xor_sync(0xffffffffu, a2, o);
        }
        if (lane == 0) { swarp[wid] = a1; scol[wid] = a2; }
        __syncthreads();
        float hp = 0.0f, sA = 0.0f;
#pragma unroll
        for (int w = 0; w < 8; ++w) { hp += swarp[w]; sA += scol[w]; }

        float t = 0.0f;
        if (tid < KDIM) {
            float dg = __ldcg(&g_diag[tid]);
            float cl = __ldcg(&g_col[tid]);
            t = dg * log2f(cl / sA + 1e-40f);
        }
#pragma unroll
        for (int o = 16; o > 0; o >>= 1) t += __shfl_xor_sync(0xffffffffu, t, o);
        __syncthreads();
        if (lane == 0) sdiag[wid] = t;
        __syncthreads();
        if (tid == 0) {
            float total = (sdiag[0] + sdiag[1] + sdiag[2] + sdiag[3]) / sA;
            int fl = flag ? *flag : 20;
            float pw = papra ? *papra : 1.0f;
            if (fl > 10) total += pw * hp;
            out[0] = total;
            if (out_size > 1) out[1] = hp;
        }
    }
}

extern "C" void kernel_launch(void* const* d_in, const int* in_sizes, int n_in,
                              void* d_out, int out_size) {
    const float* A = (const float*)d_in[0];
    const float* C = (const float*)d_in[1];
    const float* H = (const float*)d_in[2];
    const float* papra = (n_in > 3) ? (const float*)d_in[3] : nullptr;
    const int* flag = (n_in > 4) ? (const int*)d_in[4] : nullptr;

    cudaFuncSetAttribute(k_gemm, cudaFuncAttributeMaxDynamicSharedMemorySize, SMEM_BYTES);

    k_prep<<<N_FIX / 32, 256>>>(C, H);
    k_gemm<<<GRID, 256, SMEM_BYTES>>>(A, C, papra, flag, (float*)d_out, out_size);
}